// round 1
// baseline (speedup 1.0000x reference)
#include <cuda_runtime.h>
#include <math.h>

// Problem constants
#define B_  4
#define T_  4096
#define D_  512
#define BT_ (B_ * T_)          // 16384
#define N3_ (3 * D_)           // 1536
#define EPS_LN 1e-5f
#define SCALE_QK 0.04419417382415922f   // 1/sqrt(512)

// ---------------- scratch (device globals; no allocation allowed) -----------
__device__ float g_xn [ (long long)BT_ * D_  ];     //  33.5 MB  LN output
__device__ float g_qkv[ (long long)BT_ * N3_ ];     // 100.7 MB  QKV
__device__ float g_S  [ (long long)B_ * T_ * T_ ];  // 268.4 MB  scores/probs
__device__ float g_att[ (long long)BT_ * D_  ];     //  33.5 MB  attention out

// ---------------- LayerNorm: one block (128 thr) per row of 512 -------------
__global__ void ln_kernel(const float* __restrict__ x,
                          const float* __restrict__ gamma,
                          const float* __restrict__ beta,
                          float* __restrict__ xn)
{
    const long long row = blockIdx.x;
    const int tid = threadIdx.x;             // 0..127
    const float4* xr = (const float4*)(x + row * D_);
    float4 v = xr[tid];

    float s  = v.x + v.y + v.z + v.w;
    float ss = v.x*v.x + v.y*v.y + v.z*v.z + v.w*v.w;

    // warp reduce
    #pragma unroll
    for (int o = 16; o > 0; o >>= 1) {
        s  += __shfl_xor_sync(0xffffffffu, s,  o);
        ss += __shfl_xor_sync(0xffffffffu, ss, o);
    }
    __shared__ float rs[4], rss[4];
    if ((tid & 31) == 0) { rs[tid >> 5] = s; rss[tid >> 5] = ss; }
    __syncthreads();
    s  = rs[0]  + rs[1]  + rs[2]  + rs[3];
    ss = rss[0] + rss[1] + rss[2] + rss[3];

    const float mu   = s * (1.0f / D_);
    const float var  = ss * (1.0f / D_) - mu * mu;
    const float rstd = rsqrtf(var + EPS_LN);

    float4 g = ((const float4*)gamma)[tid];
    float4 b = ((const float4*)beta)[tid];
    float4 o;
    o.x = (v.x - mu) * rstd * g.x + b.x;
    o.y = (v.y - mu) * rstd * g.y + b.y;
    o.z = (v.z - mu) * rstd * g.z + b.z;
    o.w = (v.w - mu) * rstd * g.w + b.w;
    ((float4*)(xn + row * D_))[tid] = o;
}

// ---------------- SGEMM core: 128x128 block, BK=8, 256 thr, 8x8 microtile ---
#define BM 128
#define BN 128
#define BK 8
#define TM 8
#define TN 8

// C[M,N] = alpha * A[M,K] @ B[K,N]   (all row-major, per-z batch strides)
// causal_kbound: limit K to (m-tile end) -> causal P@V saving
__global__ __launch_bounds__(256, 2)
void sgemm_nn(const float* __restrict__ A, int lda, long long sA,
              const float* __restrict__ Bm, int ldb, long long sB,
              float* __restrict__ C, int ldc, long long sC,
              int M, int N, int K, float alpha, int causal_kbound)
{
    const int bx = blockIdx.x;   // n tile
    const int by = blockIdx.y;   // m tile
    const int bz = blockIdx.z;
    A  += (long long)bz * sA;
    Bm += (long long)bz * sB;
    C  += (long long)bz * sC;

    const int m0 = by * BM, n0 = bx * BN;
    int Keff = K;
    if (causal_kbound) { int kb = m0 + BM; Keff = kb < K ? kb : K; }

    __shared__ float As[BK][BM];
    __shared__ float Bs[BK][BN];

    const int tid = threadIdx.x;
    const int tx = tid & 15, ty = tid >> 4;

    const int arow = tid >> 1, acol = (tid & 1) * 4;   // A: 128 rows x 8 k
    const int brow = tid >> 5, bcol = (tid & 31) * 4;  // B: 8 k rows x 128 n

    const float* Aptr = A + (long long)(m0 + arow) * lda + acol;
    const float* Bptr = Bm + (long long)brow * ldb + n0 + bcol;

    float acc[TM][TN] = {};

    for (int k0 = 0; k0 < Keff; k0 += BK) {
        float4 av = *(const float4*)(Aptr + k0);
        As[acol + 0][arow] = av.x;
        As[acol + 1][arow] = av.y;
        As[acol + 2][arow] = av.z;
        As[acol + 3][arow] = av.w;
        float4 bv = *(const float4*)(Bptr + (long long)k0 * ldb);
        *(float4*)&Bs[brow][bcol] = bv;
        __syncthreads();

        #pragma unroll
        for (int kk = 0; kk < BK; kk++) {
            float a[TM], b[TN];
            *(float4*)&a[0] = *(const float4*)&As[kk][ty * TM];
            *(float4*)&a[4] = *(const float4*)&As[kk][ty * TM + 4];
            *(float4*)&b[0] = *(const float4*)&Bs[kk][tx * TN];
            *(float4*)&b[4] = *(const float4*)&Bs[kk][tx * TN + 4];
            #pragma unroll
            for (int i = 0; i < TM; i++)
                #pragma unroll
                for (int j = 0; j < TN; j++)
                    acc[i][j] += a[i] * b[j];
        }
        __syncthreads();
    }

    #pragma unroll
    for (int i = 0; i < TM; i++) {
        float* cr = C + (long long)(m0 + ty * TM + i) * ldc + n0 + tx * TN;
        float4 v0 = make_float4(alpha*acc[i][0], alpha*acc[i][1], alpha*acc[i][2], alpha*acc[i][3]);
        float4 v1 = make_float4(alpha*acc[i][4], alpha*acc[i][5], alpha*acc[i][6], alpha*acc[i][7]);
        *(float4*)(cr)     = v0;
        *(float4*)(cr + 4) = v1;
    }
}

// C[M,N] = alpha * A[M,K] @ B[N,K]^T  (scores). Skips tiles fully above diag.
__global__ __launch_bounds__(256, 2)
void sgemm_nt_causal(const float* __restrict__ A, int lda, long long sA,
                     const float* __restrict__ Bm, int ldb, long long sB,
                     float* __restrict__ C, int ldc, long long sC,
                     int K, float alpha)
{
    const int bx = blockIdx.x;   // n tile (key)
    const int by = blockIdx.y;   // m tile (query)
    if (bx > by) return;         // fully-masked tile: skip (softmax never reads)
    const int bz = blockIdx.z;
    A  += (long long)bz * sA;
    Bm += (long long)bz * sB;
    C  += (long long)bz * sC;

    const int m0 = by * BM, n0 = bx * BN;

    __shared__ float As[BK][BM];
    __shared__ float Bs[BK][BN];

    const int tid = threadIdx.x;
    const int tx = tid & 15, ty = tid >> 4;

    const int arow = tid >> 1, acol = (tid & 1) * 4;

    const float* Aptr = A + (long long)(m0 + arow) * lda + acol;
    const float* Bptr = Bm + (long long)(n0 + arow) * ldb + acol;

    float acc[TM][TN] = {};

    for (int k0 = 0; k0 < K; k0 += BK) {
        float4 av = *(const float4*)(Aptr + k0);
        As[acol + 0][arow] = av.x;
        As[acol + 1][arow] = av.y;
        As[acol + 2][arow] = av.z;
        As[acol + 3][arow] = av.w;
        float4 bv = *(const float4*)(Bptr + k0);
        Bs[acol + 0][arow] = bv.x;
        Bs[acol + 1][arow] = bv.y;
        Bs[acol + 2][arow] = bv.z;
        Bs[acol + 3][arow] = bv.w;
        __syncthreads();

        #pragma unroll
        for (int kk = 0; kk < BK; kk++) {
            float a[TM], b[TN];
            *(float4*)&a[0] = *(const float4*)&As[kk][ty * TM];
            *(float4*)&a[4] = *(const float4*)&As[kk][ty * TM + 4];
            *(float4*)&b[0] = *(const float4*)&Bs[kk][tx * TN];
            *(float4*)&b[4] = *(const float4*)&Bs[kk][tx * TN + 4];
            #pragma unroll
            for (int i = 0; i < TM; i++)
                #pragma unroll
                for (int j = 0; j < TN; j++)
                    acc[i][j] += a[i] * b[j];
        }
        __syncthreads();
    }

    #pragma unroll
    for (int i = 0; i < TM; i++) {
        float* cr = C + (long long)(m0 + ty * TM + i) * ldc + n0 + tx * TN;
        float4 v0 = make_float4(alpha*acc[i][0], alpha*acc[i][1], alpha*acc[i][2], alpha*acc[i][3]);
        float4 v1 = make_float4(alpha*acc[i][4], alpha*acc[i][5], alpha*acc[i][6], alpha*acc[i][7]);
        *(float4*)(cr)     = v0;
        *(float4*)(cr + 4) = v1;
    }
}

// ---------------- causal row softmax: one block (256 thr) per row -----------
__global__ void softmax_kernel(float* __restrict__ S)
{
    const long long row = blockIdx.x;            // 0..BT-1
    const int b = (int)(row >> 12);              // row / T
    const int t = (int)(row & (T_ - 1));
    float* p = S + ((long long)b * T_ + t) * T_;
    const int n = t + 1;                         // valid entries: s <= t
    const int tid = threadIdx.x;

    __shared__ float redm[8], reds[8];

    // 1. max over valid entries
    float m = -3.402823466e38f;
    for (int i = tid; i < n; i += 256) m = fmaxf(m, p[i]);
    #pragma unroll
    for (int o = 16; o > 0; o >>= 1) m = fmaxf(m, __shfl_xor_sync(0xffffffffu, m, o));
    if ((tid & 31) == 0) redm[tid >> 5] = m;
    __syncthreads();
    m = redm[0];
    #pragma unroll
    for (int i = 1; i < 8; i++) m = fmaxf(m, redm[i]);

    // 2. exp + sum, store exp in place
    float s = 0.f;
    for (int i = tid; i < n; i += 256) {
        float e = __expf(p[i] - m);
        p[i] = e;
        s += e;
    }
    #pragma unroll
    for (int o = 16; o > 0; o >>= 1) s += __shfl_xor_sync(0xffffffffu, s, o);
    if ((tid & 31) == 0) reds[tid >> 5] = s;
    __syncthreads();
    s = reds[0] + reds[1] + reds[2] + reds[3] + reds[4] + reds[5] + reds[6] + reds[7];
    const float inv = 1.0f / s;

    // 3. normalize valid entries, zero-fill masked tail (so P@V reads zeros)
    for (int i = tid; i < n; i += 256) p[i] *= inv;
    for (int i = n + tid; i < T_; i += 256) p[i] = 0.f;
}

// ---------------- launch ----------------------------------------------------
extern "C" void kernel_launch(void* const* d_in, const int* in_sizes, int n_in,
                              void* d_out, int out_size)
{
    const float* x     = (const float*)d_in[0];
    // d_in[1] = mask (causality implemented directly)
    const float* gamma = (const float*)d_in[2];
    const float* beta  = (const float*)d_in[3];
    const float* Wqkv  = (const float*)d_in[4];
    const float* Wproj = (const float*)d_in[5];
    float* out = (float*)d_out;

    float *xn, *qkv, *S, *att;
    cudaGetSymbolAddress((void**)&xn,  g_xn);
    cudaGetSymbolAddress((void**)&qkv, g_qkv);
    cudaGetSymbolAddress((void**)&S,   g_S);
    cudaGetSymbolAddress((void**)&att, g_att);

    // 1. LayerNorm
    ln_kernel<<<BT_, 128>>>(x, gamma, beta, xn);

    // 2. QKV projection: [16384,512] @ [512,1536]
    sgemm_nn<<<dim3(N3_ / BN, BT_ / BM, 1), 256>>>(
        xn, D_, 0, Wqkv, N3_, 0, qkv, N3_, 0,
        BT_, N3_, D_, 1.0f, 0);

    // 3. scores: per batch, Q @ K^T * scale (causal tile skip)
    sgemm_nt_causal<<<dim3(T_ / BN, T_ / BM, B_), 256>>>(
        qkv + 0,   N3_, (long long)T_ * N3_,     // Q
        qkv + D_,  N3_, (long long)T_ * N3_,     // K
        S, T_, (long long)T_ * T_,
        D_, SCALE_QK);

    // 4. causal row softmax (zero-fills masked tail)
    softmax_kernel<<<BT_, 256>>>(S);

    // 5. P @ V per batch, K-loop bounded at diagonal
    sgemm_nn<<<dim3(D_ / BN, T_ / BM, B_), 256>>>(
        S, T_, (long long)T_ * T_,
        qkv + 2 * D_, N3_, (long long)T_ * N3_,  // V
        att, D_, (long long)T_ * D_,
        T_, D_, T_, 1.0f, /*causal_kbound=*/1);

    // 6. output projection: [16384,512] @ [512,512]
    sgemm_nn<<<dim3(D_ / BN, BT_ / BM, 1), 256>>>(
        att, D_, 0, Wproj, D_, 0, out, D_, 0,
        BT_, D_, D_, 1.0f, 0);
}